// round 17
// baseline (speedup 1.0000x reference)
#include <cuda_runtime.h>
#include <math.h>

// Born-Wolf PSF: params (16,64,2) -> psf (16,64,25,25,25), normalized.
// TWO pairs per block (512 blocks -> single wave at 5 blocks/SM), with
// cross-pair overlap: pair0's output phase (warps 0-3, store-heavy) runs
// concurrently with pair1's J0/CS table build (warps 4-7, FMA-heavy).
// Phase internals identical to R16.

#define NHALF 13
#define NR    35
#define NRP   36
#define NI    101

typedef unsigned long long ull;

// ---------------- compile-time geometry tables ----------------
constexpr double csqrt_(double x) {
    double g = x > 1.0 ? x : 1.0;
    for (int i = 0; i < 64; ++i) g = 0.5 * (g + x / g);
    return g;
}
struct alignas(16) PixEntry { float d1, d2; int i1, pad; };
struct Tabs {
    PixEntry pix[625];
    float W[40];
    constexpr Tabs() : pix(), W() {
        double Wd[40] = {};
        for (int yy = 0; yy < 25; ++yy)
            for (int xx = 0; xx < 25; ++xx) {
                double dx = xx - 12, dy = yy - 12;
                double rp = csqrt_(dx * dx + dy * dy);
                double t2 = 2.0 * rp;
                int i1 = (int)t2;
                double d1 = t2 - (double)i1;
                int q = yy * 25 + xx;
                pix[q].d1 = (float)d1;
                pix[q].d2 = (float)(1.0 - d1);
                pix[q].i1 = i1;
                pix[q].pad = 0;
                Wd[i1]     += 1.0 - d1;
                Wd[i1 + 1] += d1;
            }
        for (int i = 0; i < 40; ++i) W[i] = (float)Wd[i];
    }
};
__device__ constexpr Tabs g_tabs{};

// ---------------- f32x2 packed helpers (sm_100+) ----------------
__device__ __forceinline__ ull pack2(float lo, float hi) {
    ull r; asm("mov.b64 %0, {%1,%2};" : "=l"(r) : "f"(lo), "f"(hi)); return r;
}
__device__ __forceinline__ void unpack2(ull v, float& lo, float& hi) {
    asm("mov.b64 {%0,%1}, %2;" : "=f"(lo), "=f"(hi) : "l"(v));
}
__device__ __forceinline__ ull ffma2(ull a, ull b, ull c) {
    ull d; asm("fma.rn.f32x2 %0, %1, %2, %3;" : "=l"(d) : "l"(a), "l"(b), "l"(c)); return d;
}
__device__ __forceinline__ ull fmul2(ull a, ull b) {
    ull d; asm("mul.rn.f32x2 %0, %1, %2;" : "=l"(d) : "l"(a), "l"(b)); return d;
}
__device__ __forceinline__ ull fadd2(ull a, ull b) {
    ull d; asm("add.rn.f32x2 %0, %1, %2;" : "=l"(d) : "l"(a), "l"(b)); return d;
}
#define C2(c) pack2((c), (c))

// Accurate sincos for |x| up to ~1000: Cody-Waite 2-pi reduction + __sincosf.
__device__ __forceinline__ void rsincos(float x, float* s, float* c) {
    float q = rintf(x * 0.15915494309189535f);
    float r = fmaf(q, -6.28125f, x);
    r = fmaf(q, -1.9353071795864769e-3f, r);
    __sincosf(r, s, c);
}

// Scalar J0 (A&S rational approx, matches reference), fast divides.
__device__ __forceinline__ float bessel_j0f(float x) {
    float ax = fabsf(x);
    if (ax <= 8.0f) {
        float y = x * x;
        float num = -184.9052456f;
        num = fmaf(num, y, 77392.33017f);
        num = fmaf(num, y, -11214424.18f);
        num = fmaf(num, y, 651619640.7f);
        num = fmaf(num, y, -13362590354.0f);
        num = fmaf(num, y, 57568490574.0f);
        float den = y + 267.8532712f;
        den = fmaf(den, y, 59272.64853f);
        den = fmaf(den, y, 9494680.718f);
        den = fmaf(den, y, 1029532985.0f);
        den = fmaf(den, y, 57568490411.0f);
        return __fdividef(num, den);
    } else {
        float z = __fdividef(8.0f, ax);
        float y2 = z * z;
        float p1 = 0.2093887211e-6f;
        p1 = fmaf(p1, y2, -0.2073370639e-5f);
        p1 = fmaf(p1, y2, 0.2734510407e-4f);
        p1 = fmaf(p1, y2, -0.1098628627e-2f);
        p1 = fmaf(p1, y2, 1.0f);
        float p2 = -0.934935152e-7f;
        p2 = fmaf(p2, y2, 0.7621095161e-6f);
        p2 = fmaf(p2, y2, -0.6911147651e-5f);
        p2 = fmaf(p2, y2, 0.1430488765e-3f);
        p2 = fmaf(p2, y2, -0.1562499995e-1f);
        float s, c;
        rsincos(ax - 0.785398164f, &s, &c);
        return rsqrtf(ax) * 0.7978845608028654f * (c * p1 - z * s * p2);
    }
}

// Packed J0 for a pair of non-negative args (x0 <= x1).
__device__ __forceinline__ void j0_pair(float x0, float x1, float& r0, float& r1) {
    if (x1 <= 8.0f) {
        ull x = pack2(x0, x1);
        ull y = fmul2(x, x);
        ull num = C2(-184.9052456f);
        num = ffma2(num, y, C2(77392.33017f));
        num = ffma2(num, y, C2(-11214424.18f));
        num = ffma2(num, y, C2(651619640.7f));
        num = ffma2(num, y, C2(-13362590354.0f));
        num = ffma2(num, y, C2(57568490574.0f));
        ull den = fadd2(y, C2(267.8532712f));
        den = ffma2(den, y, C2(59272.64853f));
        den = ffma2(den, y, C2(9494680.718f));
        den = ffma2(den, y, C2(1029532985.0f));
        den = ffma2(den, y, C2(57568490411.0f));
        float n0, n1, d0, d1;
        unpack2(num, n0, n1); unpack2(den, d0, d1);
        r0 = __fdividef(n0, d0);
        r1 = __fdividef(n1, d1);
    } else if (x0 > 8.0f) {
        float z0 = __fdividef(8.0f, x0), z1 = __fdividef(8.0f, x1);
        ull z = pack2(z0, z1);
        ull y2 = fmul2(z, z);
        ull p1 = C2(0.2093887211e-6f);
        p1 = ffma2(p1, y2, C2(-0.2073370639e-5f));
        p1 = ffma2(p1, y2, C2(0.2734510407e-4f));
        p1 = ffma2(p1, y2, C2(-0.1098628627e-2f));
        p1 = ffma2(p1, y2, C2(1.0f));
        ull p2 = C2(-0.934935152e-7f);
        p2 = ffma2(p2, y2, C2(0.7621095161e-6f));
        p2 = ffma2(p2, y2, C2(-0.6911147651e-5f));
        p2 = ffma2(p2, y2, C2(0.1430488765e-3f));
        p2 = ffma2(p2, y2, C2(-0.1562499995e-1f));
        float p1a, p1b, p2a, p2b;
        unpack2(p1, p1a, p1b); unpack2(p2, p2a, p2b);
        float s0, c0, s1, c1;
        rsincos(x0 - 0.785398164f, &s0, &c0);
        rsincos(x1 - 0.785398164f, &s1, &c1);
        r0 = rsqrtf(x0) * 0.7978845608028654f * (c0 * p1a - z0 * s0 * p2a);
        r1 = rsqrtf(x1) * 0.7978845608028654f * (c1 * p1b - z1 * s1 * p2b);
    } else {
        r0 = bessel_j0f(x0);
        r1 = bessel_j0f(x1);
    }
}

// ---- phase 1: fill A[i][r] with t in [0,nt) (nt multiple of 8) ----
__device__ __forceinline__ void do_p1(float kn, int t, int nt, float (*sA)[NRP]) {
    const int rr  = t & 7;
    const int iit = t >> 3;
    const int istride = nt >> 3;
    for (int ii = iit; ii < 51; ii += istride) {
        int i0 = 2 * ii;
        int i1 = (i0 < NI - 1) ? i0 + 1 : NI - 1;
        float rho0 = (float)i0 * 0.01f, rho1 = (float)i1 * 0.01f;
        float b0 = kn * 0.5f * rho0;
        float b1 = kn * 0.5f * rho1;
        float tw0 = (i0 == 0 || i0 == NI - 1) ? 0.005f : 0.01f;
        float m0 = rho0 * tw0;
        float m1 = rho1 * 0.01f;
        for (int r = rr; r < NR; r += 8) {
            float fr = (float)r;
            float j0a, j0b;
            j0_pair(b0 * fr, b1 * fr, j0a, j0b);
            sA[i0][r] = j0a * m0;
            if (i1 != i0) sA[i1][r] = j0b * m1;
        }
    }
}

// ---- phase 2: one thread per i in [0,101): CS table via z-rotor ----
__device__ __forceinline__ void do_p2(float kz2, int i, float4 (*sCS4)[NI]) {
    float rho = (float)i * 0.01f;
    float th = kz2 * rho * rho;
    float c1, s1;
    rsincos(th, &s1, &c1);
    float c = 1.0f, s = 0.0f;                   // z = 0
    #pragma unroll
    for (int zp = 0; zp < 7; ++zp) {
        float cn = fmaf(c, c1, -(s * s1));      // z = 2zp+1
        float sn = fmaf(s, c1,  (c * s1));
        sCS4[zp][i] = make_float4(c, s, cn, sn);
        c = fmaf(cn, c1, -(sn * s1));           // z = 2zp+2
        s = fmaf(sn, c1,  (cn * s1));
    }
}

// ---- phase 3 + combine: all 256 threads must call. On return (after its
// internal barriers) sPair + sRed are valid for this pair. ----
__device__ __forceinline__ void p3_combine(
    int tid, const float (*sA)[NRP], const float4 (*sCS4)[NI],
    float (*sPartF)[17], float2 (*sPair)[40], float* sRed)
{
    const int g   = tid >> 6;        // i-group 0..3
    const int t64 = tid & 63;
    const int lane = tid & 31;
    const bool act = (t64 < 63);
    int zp = 0, r0 = 0;
    ull re01a = 0, re23a = 0, im01a = 0, im23a = 0;
    ull re01b = 0, re23b = 0, im01b = 0, im23b = 0;
    if (act) {
        zp = t64 / 9;
        r0 = (t64 - zp * 9) * 4;
        const int ib = g * 25 + 1;    // 1, 26, 51, 76 (i=0 contributes zero)
        #pragma unroll
        for (int t = 0; t < 25; ++t) {
            const int i = ib + t;
            float4 av = *(const float4*)&sA[i][r0];
            float4 cs = sCS4[zp][i];
            ull a01 = pack2(av.x, av.y), a23 = pack2(av.z, av.w);
            ull cc0 = C2(cs.x), ss0 = C2(cs.y);
            ull cc1 = C2(cs.z), ss1 = C2(cs.w);
            re01a = ffma2(a01, cc0, re01a);
            re23a = ffma2(a23, cc0, re23a);
            im01a = ffma2(a01, ss0, im01a);
            im23a = ffma2(a23, ss0, im23a);
            re01b = ffma2(a01, cc1, re01b);
            re23b = ffma2(a23, cc1, re23b);
            im01b = ffma2(a01, ss1, im01b);
            im23b = ffma2(a23, ss1, im23b);
        }
        if (g > 0) {
            float* d = sPartF[(g - 1) * 63 + t64];
            float v0, v1;
            unpack2(re01a, v0, v1); d[0]  = v0; d[1]  = v1;
            unpack2(re23a, v0, v1); d[2]  = v0; d[3]  = v1;
            unpack2(im01a, v0, v1); d[4]  = v0; d[5]  = v1;
            unpack2(im23a, v0, v1); d[6]  = v0; d[7]  = v1;
            unpack2(re01b, v0, v1); d[8]  = v0; d[9]  = v1;
            unpack2(re23b, v0, v1); d[10] = v0; d[11] = v1;
            unpack2(im01b, v0, v1); d[12] = v0; d[13] = v1;
            unpack2(im23b, v0, v1); d[14] = v0; d[15] = v1;
        }
    }
    __syncthreads();

    float wdot = 0.0f;
    if (act && g == 0) {
        float vacc[16];
        unpack2(re01a, vacc[0], vacc[1]);   unpack2(re23a, vacc[2],  vacc[3]);
        unpack2(im01a, vacc[4], vacc[5]);   unpack2(im23a, vacc[6],  vacc[7]);
        unpack2(re01b, vacc[8], vacc[9]);   unpack2(re23b, vacc[10], vacc[11]);
        unpack2(im01b, vacc[12], vacc[13]); unpack2(im23b, vacc[14], vacc[15]);
        #pragma unroll
        for (int gg = 0; gg < 3; ++gg) {
            const float* d = sPartF[gg * 63 + t64];
            #pragma unroll
            for (int j = 0; j < 16; ++j) vacc[j] += d[j];
        }
        const int z0 = 2 * zp, z1 = z0 + 1;
        const bool hasZ1 = (z1 < NHALF);     // zp=6 has only z=12
        const float wz0 = (zp == 0) ? 1.0f : 2.0f;
        #pragma unroll
        for (int j = 0; j < 4; ++j) {
            int r = r0 + j;
            if (r < NR) {
                float P0 = vacc[j]     * vacc[j]     + vacc[4 + j]  * vacc[4 + j];
                float P1 = vacc[8 + j] * vacc[8 + j] + vacc[12 + j] * vacc[12 + j];
                sPair[z0][r].x = P0;
                if (r >= 1) sPair[z0][r - 1].y = P0;   // .y[r-1] = plane[r]
                float acc = wz0 * P0;
                if (hasZ1) {
                    sPair[z1][r].x = P1;
                    if (r >= 1) sPair[z1][r - 1].y = P1;
                    acc += 2.0f * P1;
                }
                wdot += g_tabs.W[r] * acc;
            }
        }
        // sPair[*][34].y stays unwritten; max i1 over pixels is 33 -> never read.
    }
    if (tid < 64) {
        #pragma unroll
        for (int o = 16; o; o >>= 1) wdot += __shfl_xor_sync(0xFFFFFFFFu, wdot, o);
        if (lane == 0) sRed[tid >> 5] = wdot;
    }
    __syncthreads();
}

// ---- phase 6: output writer for t in [0,nt) ----
__device__ __forceinline__ void do_p6(int t, int nt, float inv,
                                      const float2 (*sPair)[40],
                                      float* __restrict__ po) {
    const float4* ptab = reinterpret_cast<const float4*>(g_tabs.pix);
    for (int pix = t; pix < 625; pix += nt) {
        float4 e = ptab[pix];                 // {d1, d2, i1 bits, pad}
        int i1 = __float_as_int(e.z);
        float d1 = e.x * inv, d2 = e.y * inv;
        float vv[NHALF];
        #pragma unroll
        for (int zo = 0; zo < NHALF; ++zo) {
            float2 pr = sPair[zo][i1];        // LDS.64
            vv[zo] = fmaf(d1, pr.y, d2 * pr.x);
        }
        #pragma unroll
        for (int zz = 0; zz < 25; ++zz) {
            int zo = (zz < 12) ? (12 - zz) : (zz - 12);
            po[zz * 625 + pix] = vv[zo];
        }
    }
}

__global__ __launch_bounds__(256, 5)
void bw_psf_kernel(const float* __restrict__ params, float* __restrict__ out,
                   int npairs) {
    const int tid = threadIdx.x;

    __shared__ __align__(16) float  sA[NI][NRP];     // 14.5 KB (reused per pair)
    __shared__ __align__(16) float4 sCS4[7][NI];     // 11.3 KB (reused)
    __shared__ float2 sPair[NHALF][40];              // 4.2 KB (reused)
    __shared__ float  sPartF[3 * 63][17];            // 12.9 KB (scratch)
    __shared__ float  sRed[2];

    const int pr0 = blockIdx.x * 2;
    const int pr1 = pr0 + 1;
    const bool have1 = (pr1 < npairs);

    // pair0 constants
    const float lam0 = fabsf(params[2 * pr0]);
    const float nn0  = fabsf(params[2 * pr0 + 1]);
    const float k0   = 6.2831853071795864769f / lam0;
    const float kn0  = k0 * nn0;
    const float kz20 = 0.5f * k0 * nn0 * nn0;
    // pair1 constants
    float kn1 = 0.0f, kz21 = 0.0f;
    if (have1) {
        const float lam1 = fabsf(params[2 * pr1]);
        const float nn1  = fabsf(params[2 * pr1 + 1]);
        const float k1   = 6.2831853071795864769f / lam1;
        kn1  = k1 * nn1;
        kz21 = 0.5f * k1 * nn1 * nn1;
    }

    // ---- Stage 1: pair0 J0 table (all 256) + CS table (threads 128..228) ----
    do_p1(kn0, tid, 256, sA);
    if (tid >= 128 && tid < 128 + NI) do_p2(kz20, tid - 128, sCS4);
    __syncthreads();

    // ---- Stage 2+3: pair0 matmul + combine (has internal barriers) ----
    p3_combine(tid, sA, sCS4, sPartF, sPair, sRed);

    // ---- Stage 4 (overlap): warps 0-3 write pair0 output;
    //      warps 4-7 build pair1's J0 + CS tables (sA/sCS4 are dead) ----
    if (tid < 128) {
        const float inv0 = __fdividef(1.0f, sRed[0] + sRed[1]);
        do_p6(tid, 128, inv0, sPair, out + (size_t)pr0 * 15625);
    } else if (have1) {
        do_p1(kn1, tid - 128, 128, sA);
        if (tid < 128 + NI) do_p2(kz21, tid - 128, sCS4);
    }
    __syncthreads();

    if (!have1) return;

    // ---- Stage 5+6: pair1 matmul + combine ----
    p3_combine(tid, sA, sCS4, sPartF, sPair, sRed);

    // ---- Stage 7: pair1 output on all 256 threads ----
    const float inv1 = __fdividef(1.0f, sRed[0] + sRed[1]);
    do_p6(tid, 256, inv1, sPair, out + (size_t)pr1 * 15625);
}

extern "C" void kernel_launch(void* const* d_in, const int* in_sizes, int n_in,
                              void* d_out, int out_size) {
    const float* params = (const float*)d_in[0];
    float* out = (float*)d_out;
    int npairs = in_sizes[0] / 2;   // 16*64 = 1024
    int nblk = (npairs + 1) / 2;    // 512: single wave at 5 blocks/SM
    bw_psf_kernel<<<nblk, 256>>>(params, out, npairs);
}